// round 1
// baseline (speedup 1.0000x reference)
#include <cuda_runtime.h>

#define Z 64      // z_dim
#define H 256     // hidden
#define C 5       // num classes
#define GMAX 16

__device__ float g_S[GMAX * C * Z];
__device__ int   g_cnt[C];
__device__ __align__(16) float g_D[GMAX * C * Z];

// ---------------------------------------------------------------- zero scratch
__global__ void zero_kernel() {
    int t = threadIdx.x;
    for (int i = t; i < GMAX * C * Z; i += blockDim.x) g_S[i] = 0.f;
    if (t < C) g_cnt[t] = 0;
}

// ------------------------------------------------------- per-class sum of x
// grid: (nChunks, G+1). blockIdx.y == G  -> label counting blocks.
// 256 threads = 4 groups of 64 lanes; lane = feature dim d, group strides nodes.
__global__ void reduce_kernel(const float* __restrict__ x,
                              const int*   __restrict__ label,
                              int N, int chunk) {
    int g  = blockIdx.y;
    int n0 = blockIdx.x * chunk;
    int n1 = min(n0 + chunk, N);

    if (g == (int)gridDim.y - 1) {
        // counting blocks
        int cnt[C];
#pragma unroll
        for (int c = 0; c < C; c++) cnt[c] = 0;
        for (int n = n0 + threadIdx.x; n < n1; n += blockDim.x) {
            int c = __ldg(label + n);
#pragma unroll
            for (int cc = 0; cc < C; cc++) cnt[cc] += (cc == c);
        }
        __shared__ int scnt[C];
        if (threadIdx.x < C) scnt[threadIdx.x] = 0;
        __syncthreads();
#pragma unroll
        for (int cc = 0; cc < C; cc++)
            if (cnt[cc]) atomicAdd(&scnt[cc], cnt[cc]);
        __syncthreads();
        if (threadIdx.x < C) atomicAdd(&g_cnt[threadIdx.x], scnt[threadIdx.x]);
        return;
    }

    int lane = threadIdx.x & 63;
    int grp  = threadIdx.x >> 6;

    float acc[C];
#pragma unroll
    for (int c = 0; c < C; c++) acc[c] = 0.f;

    const float* xg = x + (size_t)g * N * Z;
#pragma unroll 4
    for (int n = n0 + grp; n < n1; n += 4) {
        int   c = __ldg(label + n);
        float v = __ldg(xg + (size_t)n * Z + lane);
#pragma unroll
        for (int cc = 0; cc < C; cc++)
            acc[cc] += (cc == c) ? v : 0.f;
    }

    __shared__ float sacc[4][C][64];
#pragma unroll
    for (int c = 0; c < C; c++) sacc[grp][c][lane] = acc[c];
    __syncthreads();

    for (int t = threadIdx.x; t < C * 64; t += blockDim.x) {
        int c = t >> 6, d = t & 63;
        float v = sacc[0][c][d] + sacc[1][c][d] + sacc[2][c][d] + sacc[3][c][d];
        atomicAdd(&g_S[(g * C + c) * Z + d], v);
    }
}

// ----------------------------------------- tiny 2-layer GEMM over 80 rows
// block r = g*C + c computes D[r,:] = relu((S[r]/cnt) @ W1 + b1) @ W2 + b2
__global__ void mid_kernel(const float* __restrict__ W1,
                           const float* __restrict__ b1,
                           const float* __restrict__ W2,
                           const float* __restrict__ b2) {
    int r   = blockIdx.x;
    int c   = r % C;
    int tid = threadIdx.x;

    __shared__ float s_inv;
    __shared__ float s[Z];
    __shared__ float h[H];
    __shared__ float part[4][Z];

    if (tid == 0) s_inv = 1.f / (float)max(g_cnt[c], 1);
    __syncthreads();
    if (tid < Z) s[tid] = g_S[r * Z + tid] * s_inv;
    __syncthreads();

    // layer 1: h[j] = relu(sum_d s[d] * W1[d,j] + b1[j]), tid = j
    float acc = __ldg(b1 + tid);
#pragma unroll
    for (int d = 0; d < Z; d++)
        acc = fmaf(s[d], __ldg(W1 + d * H + tid), acc);
    h[tid] = fmaxf(acc, 0.f);
    __syncthreads();

    // layer 2: D[k] = sum_j h[j] * W2[j,k] + b2[k]
    int lane = tid & 63, grp = tid >> 6;
    float p = 0.f;
#pragma unroll
    for (int j = 0; j < 64; j++) {
        int jj = grp * 64 + j;
        p = fmaf(h[jj], __ldg(W2 + jj * Z + lane), p);
    }
    part[grp][lane] = p;
    __syncthreads();
    if (tid < Z) {
        float d = __ldg(b2 + tid) + part[0][tid] + part[1][tid]
                + part[2][tid] + part[3][tid];
        g_D[r * Z + tid] = d;
    }
}

// ------------------------------------ out[g,n,:] = x[g,n,:] + D[g,label[n],:]
// float4 path: 16 lanes cover one 64-float row, 16 groups stride rows.
__global__ void out_kernel(const float* __restrict__ x,
                           const int*   __restrict__ label,
                           float*       __restrict__ out,
                           int N, int chunk) {
    int g = blockIdx.y;
    __shared__ float4 sD[C * 16];
    if (threadIdx.x < C * 16)
        sD[threadIdx.x] =
            reinterpret_cast<const float4*>(g_D)[g * C * 16 + threadIdx.x];
    __syncthreads();

    int lane = threadIdx.x & 15;
    int grp  = threadIdx.x >> 4;
    int n0 = blockIdx.x * chunk;
    int n1 = min(n0 + chunk, N);

    const float4* x4 = reinterpret_cast<const float4*>(x);
    float4*       o4 = reinterpret_cast<float4*>(out);

    for (int n = n0 + grp; n < n1; n += 16) {
        int    c   = __ldg(label + n);
        size_t idx = ((size_t)g * N + n) * 16 + lane;
        float4 xv  = __ldg(x4 + idx);
        float4 dv  = sD[c * 16 + lane];
        float4 rv;
        rv.x = xv.x + dv.x;
        rv.y = xv.y + dv.y;
        rv.z = xv.z + dv.z;
        rv.w = xv.w + dv.w;
        o4[idx] = rv;
    }
}

// ---------------------------------------------------------------- launcher
extern "C" void kernel_launch(void* const* d_in, const int* in_sizes, int n_in,
                              void* d_out, int out_size) {
    const float* x     = (const float*)d_in[0];
    const int*   label = (const int*)  d_in[1];
    const float* W1    = (const float*)d_in[2];
    const float* b1    = (const float*)d_in[3];
    const float* W2    = (const float*)d_in[4];
    const float* b2    = (const float*)d_in[5];
    float*       out   = (float*)d_out;

    int N = in_sizes[1];                 // 40000
    int G = in_sizes[0] / (N * Z);       // 16

    zero_kernel<<<1, 256>>>();

    int chunk1 = 544;                    // multiple of 4
    dim3 grid1((N + chunk1 - 1) / chunk1, G + 1);
    reduce_kernel<<<grid1, 256>>>(x, label, N, chunk1);

    mid_kernel<<<G * C, 256>>>(W1, b1, W2, b2);

    int chunk3 = 320;                    // multiple of 16
    dim3 grid3((N + chunk3 - 1) / chunk3, G);
    out_kernel<<<grid3, 256>>>(x, label, out, N, chunk3);
}